// round 11
// baseline (speedup 1.0000x reference)
#include <cuda_runtime.h>
#include <math.h>
#include <stdint.h>

#define S_LEN  2048
#define DMODEL 1024
#define NHEAD  16
#define DK     64
#define B_SZ   2
#define M_TOT  (B_SZ * S_LEN)      // 4096
#define BH_TOT (B_SZ * NHEAD)      // 32

// ------------------------- scratch (device globals; no allocs allowed) ------
// Q,K: [b,h,s,dk] tf32 (Q pre-scaled 1/8). V: [b,h,d,s] tf32. O: [b,s,d] tf32.
// X: tf32(x). Wr: tf32(Wq|Wk|Wv|Wo) concatenated.
__device__ float g_Q[(size_t)BH_TOT * S_LEN * DK];
__device__ float g_K[(size_t)BH_TOT * S_LEN * DK];
__device__ float g_V[(size_t)BH_TOT * S_LEN * DK];
__device__ float g_O[(size_t)M_TOT * DMODEL];
__device__ float g_X[(size_t)M_TOT * DMODEL];
__device__ float g_Wr[(size_t)4 * DMODEL * DMODEL];

// ======================= helpers =============================================
__device__ __forceinline__ uint32_t smem_u32(const void* p) {
    uint32_t a;
    asm("{ .reg .u64 t; cvta.to.shared.u64 t, %1; cvt.u32.u64 %0, t; }"
        : "=r"(a) : "l"(p));
    return a;
}
__device__ __forceinline__ uint32_t f32_to_tf32(float f) {
    uint32_t r;
    asm("cvt.rna.tf32.f32 %0, %1;" : "=r"(r) : "f"(f));
    return r;
}
__device__ __forceinline__ float tf32r(float f) {
    return __uint_as_float(f32_to_tf32(f));
}
__device__ __forceinline__ void ldsm4(uint32_t r[4], uint32_t addr) {
    asm volatile("ldmatrix.sync.aligned.m8n8.x4.shared.b16 {%0,%1,%2,%3}, [%4];"
                 : "=r"(r[0]), "=r"(r[1]), "=r"(r[2]), "=r"(r[3]) : "r"(addr));
}
__device__ __forceinline__ void mma_tf32(float d[4], const uint32_t a[4],
                                         const uint32_t b[2]) {
    asm volatile("mma.sync.aligned.m16n8k8.row.col.f32.tf32.tf32.f32 "
                 "{%0,%1,%2,%3}, {%4,%5,%6,%7}, {%8,%9}, {%0,%1,%2,%3};"
                 : "+f"(d[0]), "+f"(d[1]), "+f"(d[2]), "+f"(d[3])
                 : "r"(a[0]), "r"(a[1]), "r"(a[2]), "r"(a[3]),
                   "r"(b[0]), "r"(b[1]));
}
#define CP_ASYNC16(dst, src) \
    asm volatile("cp.async.cg.shared.global [%0], [%1], 16;" \
                 :: "r"(dst), "l"(src) : "memory")
#define CP_COMMIT() asm volatile("cp.async.commit_group;" ::: "memory")
#define CP_WAIT0()  asm volatile("cp.async.wait_group 0;" ::: "memory")
#define CP_WAIT1()  asm volatile("cp.async.wait_group 1;" ::: "memory")
#define CP_WAIT2()  asm volatile("cp.async.wait_group 2;" ::: "memory")

// ======================= pre-pass: round x, W to tf32 ========================
__global__ __launch_bounds__(256) void prepass_kernel(
    const float4* __restrict__ x,  const float4* __restrict__ wq,
    const float4* __restrict__ wk, const float4* __restrict__ wv,
    const float4* __restrict__ wo)
{
    int idx = blockIdx.x * 256 + threadIdx.x;   // 0 .. 2097151
    float4 v; float4* dst;
    if (idx < 1048576) {
        v = x[idx]; dst = (float4*)g_X + idx;
    } else {
        int r = idx - 1048576;
        int which = r >> 18, off = r & 262143;
        const float4* src = (which == 0) ? wq : (which == 1) ? wk
                          : (which == 2) ? wv : wo;
        v = src[off];
        dst = (float4*)g_Wr + ((size_t)which << 18) + off;
    }
    v.x = tf32r(v.x); v.y = tf32r(v.y); v.z = tf32r(v.z); v.w = tf32r(v.w);
    *dst = v;
}

// ======================= tf32 GEMM (cp.async, 3-stage) =======================
// C[m,n] = sum_k A[m,k] * W[n,k]. Tile 128x128, BK=32, 8 warps (2m x 4n).
// 3-stage cp.async ring: copy(t+2) issued each iter; wait_group 2 -> tile t
// resident with two iterations of prefetch slack.
#define PA 36
#define GTILE (128 * PA)
#define GSTAGE (2 * GTILE)               // A+B per stage (floats)
#define GSMEM (3 * GSTAGE * 4)           // 110592 B

__global__ void __launch_bounds__(256, 2) gemm_kernel(float* __restrict__ out,
                                                      int job)
{
    extern __shared__ float smg[];
    const uint32_t sG = smem_u32(smg);

    const int tid = threadIdx.x;
    const int wid = tid >> 5, lane = tid & 31;
    const int wm = (wid >> 2) * 64;
    const int wn = (wid & 3) * 32;
    const int bm = blockIdx.y * 128;

    int bn, mode;
    const float *Ap, *Wp;
    if (job == 0) {
        Ap = g_O; Wp = g_Wr + 3 * 1048576; mode = 0; bn = blockIdx.x * 128;
    } else {
        int which = blockIdx.x >> 3;
        bn = (blockIdx.x & 7) * 128;
        Ap = g_X; Wp = g_Wr + (size_t)which * 1048576;
        mode = (which == 2) ? 1 : which + 2;   // 0->Q(2), 1->K(3), 2->V(1)
    }

    const int q = lane >> 3, rq = lane & 7;
    const int qm = (q & 1) * 8, qk = (q & 2) * 2;
    const int brow = (lane & 7) + ((lane >> 4) << 3);
    const int bcol = ((lane >> 3) & 1) * 4;
    const int cr = tid >> 3, cch = tid & 7;

    // copy k-tile t into stage s
    #define G_COPY(t, s) do {                                                  \
        uint32_t ab = sG + (uint32_t)((s) * GSTAGE) * 4;                       \
        uint32_t bb = ab + (uint32_t)GTILE * 4;                                \
        uint32_t doff = (uint32_t)(cr * PA + cch * 4) * 4;                     \
        int k0_ = (t) * 32;                                                    \
        _Pragma("unroll")                                                      \
        for (int i_ = 0; i_ < 4; i_++) {                                       \
            int r_ = cr + i_ * 32;                                             \
            CP_ASYNC16(ab + doff + (uint32_t)(i_ * 32 * PA) * 4,               \
                       Ap + (size_t)(bm + r_) * DMODEL + k0_ + cch * 4);       \
            CP_ASYNC16(bb + doff + (uint32_t)(i_ * 32 * PA) * 4,               \
                       Wp + (size_t)(bn + r_) * DMODEL + k0_ + cch * 4);       \
        }                                                                      \
        CP_COMMIT();                                                           \
    } while (0)

    float acc[4][4][4];
    #pragma unroll
    for (int mt = 0; mt < 4; mt++)
        #pragma unroll
        for (int nt = 0; nt < 4; nt++)
            #pragma unroll
            for (int i = 0; i < 4; i++) acc[mt][nt][i] = 0.f;

    // prologue: tiles 0,1 into stages 0,1
    G_COPY(0, 0);
    G_COPY(1, 1);

    int stage = 0, nstage = 2;   // nstage = stage of tile t+2
    for (int t = 0; t < 32; t++) {
        if (t < 30) {
            G_COPY(t + 2, nstage);   // overwrites stage of tile t-1 (barrier-safe)
            CP_WAIT2();
        } else if (t == 30) {
            CP_WAIT1();
        } else {
            CP_WAIT0();
        }
        __syncthreads();

        const uint32_t aB = sG + (uint32_t)(stage * GSTAGE) * 4;
        const uint32_t bB = aB + (uint32_t)GTILE * 4;
        #pragma unroll
        for (int ks = 0; ks < 4; ks++) {
            uint32_t aR[4][4], b0[4], b1[4];
            #pragma unroll
            for (int mt = 0; mt < 4; mt++)
                ldsm4(aR[mt], aB + (uint32_t)((wm + mt * 16 + qm + rq) * PA +
                                              ks * 8 + qk) * 4);
            ldsm4(b0, bB + (uint32_t)((wn + brow) * PA + ks * 8 + bcol) * 4);
            ldsm4(b1, bB + (uint32_t)((wn + 16 + brow) * PA + ks * 8 + bcol) * 4);
            #pragma unroll
            for (int mt = 0; mt < 4; mt++) {
                mma_tf32(acc[mt][0], aR[mt], &b0[0]);
                mma_tf32(acc[mt][1], aR[mt], &b0[2]);
                mma_tf32(acc[mt][2], aR[mt], &b1[0]);
                mma_tf32(acc[mt][3], aR[mt], &b1[2]);
            }
        }
        __syncthreads();
        stage = (stage == 2) ? 0 : stage + 1;
        nstage = (nstage == 2) ? 0 : nstage + 1;
    }
    #undef G_COPY

    const float kf = 0.28782313662425573f;
    #pragma unroll
    for (int mt = 0; mt < 4; mt++) {
        #pragma unroll
        for (int nt = 0; nt < 4; nt++) {
            float* a = acc[mt][nt];
            const int col = bn + wn + nt * 8 + 2 * (lane & 3);
            const int rbase = bm + wm + mt * 16 + (lane >> 2);
            if (mode == 0) {
                *(float2*)(out + (size_t)rbase * DMODEL + col) =
                    make_float2(a[0], a[1]);
                *(float2*)(out + (size_t)(rbase + 8) * DMODEL + col) =
                    make_float2(a[2], a[3]);
            } else if (mode == 1) {
                const int h = col >> 6, d = col & 63;
                #pragma unroll
                for (int rr = 0; rr < 2; rr++) {
                    int m = rbase + rr * 8;
                    int b = m >> 11, s = m & 2047;
                    float* base = g_V + ((size_t)(b * NHEAD + h) * DK) * S_LEN;
                    base[(size_t)d * S_LEN + s]       = tf32r(a[rr * 2]);
                    base[(size_t)(d + 1) * S_LEN + s] = tf32r(a[rr * 2 + 1]);
                }
            } else {
                const int h = col >> 6, d = col & 63;
                const float qs = (mode == 2) ? 0.125f : 1.0f;
                float* dst = (mode == 2) ? g_Q : g_K;
                float fr = expf(-(float)(d >> 1) * kf);
                #pragma unroll
                for (int rr = 0; rr < 2; rr++) {
                    int m = rbase + rr * 8;
                    int b = m >> 11, s = m & 2047;
                    float e = a[rr * 2], o = a[rr * 2 + 1];
                    float sn, cs;
                    sincosf((float)s * fr, &sn, &cs);
                    float2 v = make_float2(tf32r((e * cs - o * sn) * qs),
                                           tf32r((e * sn + o * cs) * qs));
                    *(float2*)(dst + ((size_t)(b * NHEAD + h) * S_LEN + s) * DK + d) = v;
                }
            }
        }
    }
}

// ================= causal flash attention, kv-pipelined ======================
// Iter j: softmax(S(j)) [tensor drains PV(j-1)] -> stage P -> S-mma(j+1) -> PV(j).
// Tile t lives in buf t&1; copy(j+2) issued after end-of-iter barrier.
#define KP 68
#define PP 68
#define KV_TILE_F (64 * KP)
#define BUF_F     (2 * KV_TILE_F)
#define FLASH_SMEM ((2 * BUF_F + 128 * PP) * 4)   // 104448 B

__global__ void __launch_bounds__(256, 2) flash_kernel()
{
    extern __shared__ float smf[];
    float* Ps = smf + 2 * BUF_F;
    const uint32_t sK = smem_u32(smf);
    const uint32_t sP = smem_u32(Ps);

    const int qt = 15 - blockIdx.y;     // big tiles first (bh fastest)
    const int bh = blockIdx.x;
    const float* Qp  = g_Q + (size_t)bh * S_LEN * DK;
    const float* Kp  = g_K + (size_t)bh * S_LEN * DK;
    const float* Vtp = g_V + (size_t)bh * S_LEN * DK;   // [d][s]

    const int tid = threadIdx.x;
    const int wid = tid >> 5, lane = tid & 31;
    const int q = lane >> 3, rq = lane & 7;
    const int qm = (q & 1) * 8, qk = (q & 2) * 2;
    const int lq = lane >> 2, lc = lane & 3;
    const int brow = (lane & 7) + ((lane >> 4) << 3);
    const int bcol = ((lane >> 3) & 1) * 4;
    const int cr = tid >> 4, cc = tid & 15;

    const int nkt = 2 * qt + 2;

    #define COPY_TILE(t, b) do {                                               \
        uint32_t kb = sK + (uint32_t)((b) * BUF_F) * 4;                        \
        uint32_t vb = kb + (uint32_t)KV_TILE_F * 4;                            \
        uint32_t doff = (uint32_t)(cr * KP + cc * 4) * 4;                      \
        const float* Kn = Kp + (size_t)(t) * 64 * DK;                          \
        const float* Vn = Vtp + (size_t)(t) * 64;                              \
        _Pragma("unroll")                                                      \
        for (int i_ = 0; i_ < 4; i_++) {                                       \
            int r_ = cr + i_ * 16;                                             \
            CP_ASYNC16(kb + doff + (uint32_t)(i_ * 16 * KP) * 4,               \
                       Kn + (size_t)r_ * DK + cc * 4);                         \
            CP_ASYNC16(vb + doff + (uint32_t)(i_ * 16 * KP) * 4,               \
                       Vn + (size_t)r_ * S_LEN + cc * 4);                      \
        }                                                                      \
        CP_COMMIT();                                                           \
    } while (0)

    #define S_MMA(b) do {                                                      \
        const uint32_t sKb_ = sK + (uint32_t)((b) * BUF_F) * 4;                \
        _Pragma("unroll")                                                      \
        for (int nt_ = 0; nt_ < 8; nt_++)                                      \
            _Pragma("unroll")                                                  \
            for (int j_ = 0; j_ < 4; j_++) s[nt_][j_] = 0.f;                   \
        _Pragma("unroll")                                                      \
        for (int ks_ = 0; ks_ < 8; ks_++) {                                    \
            _Pragma("unroll")                                                  \
            for (int n2_ = 0; n2_ < 4; n2_++) {                                \
                uint32_t bb_[4];                                               \
                ldsm4(bb_, sKb_ + (uint32_t)((n2_ * 16 + brow) * KP +          \
                                             ks_ * 8 + bcol) * 4);             \
                mma_tf32(s[2 * n2_],     qf[ks_], &bb_[0]);                    \
                mma_tf32(s[2 * n2_ + 1], qf[ks_], &bb_[2]);                    \
            }                                                                  \
        }                                                                      \
    } while (0)

    COPY_TILE(0, 0);
    COPY_TILE(1, 1);

    #pragma unroll
    for (int i = 0; i < 8; i++) {
        int f = tid + i * 256;
        int r = f >> 4, c = f & 15;
        float4 v = *(const float4*)(Qp + (size_t)(qt * 128 + r) * DK + c * 4);
        *(float4*)&Ps[r * PP + c * 4] = v;
    }
    __syncthreads();
    uint32_t qf[8][4];
    {
        uint32_t base = sP + (uint32_t)((wid * 16 + qm + rq) * PP + qk) * 4;
        #pragma unroll
        for (int ks = 0; ks < 8; ks++) ldsm4(qf[ks], base + ks * 32);
    }

    float m1 = -INFINITY, m2 = -INFINITY, l1 = 0.f, l2 = 0.f;
    float o[8][4];
    #pragma unroll
    for (int nt = 0; nt < 8; nt++)
        #pragma unroll
        for (int j = 0; j < 4; j++) o[nt][j] = 0.f;

    float s[8][4];
    CP_WAIT1();
    __syncthreads();
    S_MMA(0);

    for (int j = 0; j < nkt; j++) {
        if (j >= 2 * qt) {
            const int row1 = qt * 128 + wid * 16 + lq;
            #pragma unroll
            for (int nt = 0; nt < 8; nt++) {
                int colb = j * 64 + nt * 8 + 2 * lc;
                if (colb     > row1)     s[nt][0] = -INFINITY;
                if (colb + 1 > row1)     s[nt][1] = -INFINITY;
                if (colb     > row1 + 8) s[nt][2] = -INFINITY;
                if (colb + 1 > row1 + 8) s[nt][3] = -INFINITY;
            }
        }

        float mx1 = -INFINITY, mx2 = -INFINITY;
        #pragma unroll
        for (int nt = 0; nt < 8; nt++) {
            mx1 = fmaxf(mx1, fmaxf(s[nt][0], s[nt][1]));
            mx2 = fmaxf(mx2, fmaxf(s[nt][2], s[nt][3]));
        }
        mx1 = fmaxf(mx1, __shfl_xor_sync(0xffffffffu, mx1, 1));
        mx1 = fmaxf(mx1, __shfl_xor_sync(0xffffffffu, mx1, 2));
        mx2 = fmaxf(mx2, __shfl_xor_sync(0xffffffffu, mx2, 1));
        mx2 = fmaxf(mx2, __shfl_xor_sync(0xffffffffu, mx2, 2));
        const float nm1 = fmaxf(m1, mx1), nm2 = fmaxf(m2, mx2);
        const float sc1 = __expf(m1 - nm1), sc2 = __expf(m2 - nm2);
        float su1 = 0.f, su2 = 0.f;
        #pragma unroll
        for (int nt = 0; nt < 8; nt++) {
            s[nt][0] = __expf(s[nt][0] - nm1); su1 += s[nt][0];
            s[nt][1] = __expf(s[nt][1] - nm1); su1 += s[nt][1];
            s[nt][2] = __expf(s[nt][2] - nm2); su2 += s[nt][2];
            s[nt][3] = __expf(s[nt][3] - nm2); su2 += s[nt][3];
        }
        su1 += __shfl_xor_sync(0xffffffffu, su1, 1);
        su1 += __shfl_xor_sync(0xffffffffu, su1, 2);
        su2 += __shfl_xor_sync(0xffffffffu, su2, 1);
        su2 += __shfl_xor_sync(0xffffffffu, su2, 2);
        l1 = l1 * sc1 + su1;  m1 = nm1;
        l2 = l2 * sc2 + su2;  m2 = nm2;
        #pragma unroll
        for (int nt = 0; nt < 8; nt++) {
            o[nt][0] *= sc1; o[nt][1] *= sc1;
            o[nt][2] *= sc2; o[nt][3] *= sc2;
        }

        {
            uint32_t p1 = sP + (uint32_t)((wid * 16 + lq) * PP + 2 * lc) * 4;
            uint32_t p2 = p1 + (uint32_t)(8 * PP) * 4;
            #pragma unroll
            for (int nt = 0; nt < 8; nt++) {
                asm volatile("st.shared.v2.b32 [%0], {%1, %2};"
                    :: "r"(p1 + nt * 32),
                       "r"(f32_to_tf32(s[nt][0])), "r"(f32_to_tf32(s[nt][1])) : "memory");
                asm volatile("st.shared.v2.b32 [%0], {%1, %2};"
                    :: "r"(p2 + nt * 32),
                       "r"(f32_to_tf32(s[nt][2])), "r"(f32_to_tf32(s[nt][3])) : "memory");
            }
        }
        __syncwarp();

        if (j + 1 < nkt) {
            CP_WAIT0();
            __syncthreads();
            S_MMA((j + 1) & 1);
        }

        {
            const uint32_t sVb = sK + (uint32_t)((j & 1) * BUF_F +
                                                 KV_TILE_F) * 4;
            uint32_t pbase = sP + (uint32_t)((wid * 16 + qm + rq) * PP + qk) * 4;
            #pragma unroll
            for (int ks = 0; ks < 8; ks++) {
                uint32_t pf[4];
                ldsm4(pf, pbase + ks * 32);
                #pragma unroll
                for (int n2 = 0; n2 < 4; n2++) {
                    uint32_t bb[4];
                    ldsm4(bb, sVb + (uint32_t)((n2 * 16 + brow) * KP +
                                               ks * 8 + bcol) * 4);
                    mma_tf32(o[2 * n2],     pf, &bb[0]);
                    mma_tf32(o[2 * n2 + 1], pf, &bb[2]);
                }
            }
        }

        __syncthreads();
        if (j + 2 < nkt) COPY_TILE(j + 2, j & 1);
    }

    const float i1 = 1.f / l1, i2 = 1.f / l2;
    const int b = bh >> 4, h = bh & 15;
    const int row1 = qt * 128 + wid * 16 + lq;
    const size_t base1 = ((size_t)(b * S_LEN + row1)) * DMODEL + h * 64 + 2 * lc;
    const size_t base2 = base1 + (size_t)8 * DMODEL;
    #pragma unroll
    for (int nt = 0; nt < 8; nt++) {
        *(float2*)(g_O + base1 + nt * 8) =
            make_float2(tf32r(o[nt][0] * i1), tf32r(o[nt][1] * i1));
        *(float2*)(g_O + base2 + nt * 8) =
            make_float2(tf32r(o[nt][2] * i2), tf32r(o[nt][3] * i2));
    }
    #undef COPY_TILE
    #undef S_MMA
}

// ------------------------- launch -------------------------------------------
extern "C" void kernel_launch(void* const* d_in, const int* in_sizes, int n_in,
                              void* d_out, int out_size)
{
    const float* x  = (const float*)d_in[0];
    const float* Wq = (const float*)d_in[1];
    const float* Wk = (const float*)d_in[2];
    const float* Wv = (const float*)d_in[3];
    const float* Wo = (const float*)d_in[4];
    float* out = (float*)d_out;

    cudaFuncSetAttribute(gemm_kernel,
                         cudaFuncAttributeMaxDynamicSharedMemorySize, GSMEM);
    cudaFuncSetAttribute(flash_kernel,
                         cudaFuncAttributeMaxDynamicSharedMemorySize, FLASH_SMEM);

    prepass_kernel<<<8192, 256>>>((const float4*)x, (const float4*)Wq,
                                  (const float4*)Wk, (const float4*)Wv,
                                  (const float4*)Wo);

    dim3 qkv_grid(24, 32);                   // 3 projections x 8 n-blocks
    gemm_kernel<<<qkv_grid, 256, GSMEM>>>(nullptr, 1);

    dim3 fgrid(32, 16);                      // bh fastest; qt = 15 - y
    flash_kernel<<<fgrid, 256, FLASH_SMEM>>>();

    dim3 ogrid(8, 32);
    gemm_kernel<<<ogrid, 256, GSMEM>>>(out, 0);
}

// round 17
// speedup vs baseline: 1.7506x; 1.7506x over previous
#include <cuda_runtime.h>
#include <cuda_fp16.h>
#include <math.h>
#include <stdint.h>

#define S_LEN  2048
#define DMODEL 1024
#define NHEAD  16
#define DK     64
#define B_SZ   2
#define M_TOT  (B_SZ * S_LEN)      // 4096
#define BH_TOT (B_SZ * NHEAD)      // 32

// ------------------------- scratch (device globals; no allocs allowed) ------
// Qh,Kh: [b,h,s,dk] fp16 (Q pre-scaled 1/8). Vh: [b,h,d,s] fp16 (transposed).
// Oh: [b,s,d] fp16. Xh: fp16(x). Wh: fp16(Wq|Wk|Wv|Wo).
__device__ __half g_Qh[(size_t)BH_TOT * S_LEN * DK];
__device__ __half g_Kh[(size_t)BH_TOT * S_LEN * DK];
__device__ __half g_Vh[(size_t)BH_TOT * S_LEN * DK];
__device__ __half g_Oh[(size_t)M_TOT * DMODEL];
__device__ __half g_Xh[(size_t)M_TOT * DMODEL];
__device__ __half g_Wh[(size_t)4 * DMODEL * DMODEL];

// ======================= helpers =============================================
__device__ __forceinline__ uint32_t smem_u32(const void* p) {
    uint32_t a;
    asm("{ .reg .u64 t; cvta.to.shared.u64 t, %1; cvt.u32.u64 %0, t; }"
        : "=r"(a) : "l"(p));
    return a;
}
__device__ __forceinline__ uint32_t pack2(float a, float b) {
    __half2 h = __floats2half2_rn(a, b);
    return *(uint32_t*)&h;
}
__device__ __forceinline__ void ldsm4(uint32_t r[4], uint32_t addr) {
    asm volatile("ldmatrix.sync.aligned.m8n8.x4.shared.b16 {%0,%1,%2,%3}, [%4];"
                 : "=r"(r[0]), "=r"(r[1]), "=r"(r[2]), "=r"(r[3]) : "r"(addr));
}
__device__ __forceinline__ void mma_f16(float d[4], const uint32_t a[4],
                                        const uint32_t b[2]) {
    asm volatile("mma.sync.aligned.m16n8k16.row.col.f32.f16.f16.f32 "
                 "{%0,%1,%2,%3}, {%4,%5,%6,%7}, {%8,%9}, {%0,%1,%2,%3};"
                 : "+f"(d[0]), "+f"(d[1]), "+f"(d[2]), "+f"(d[3])
                 : "r"(a[0]), "r"(a[1]), "r"(a[2]), "r"(a[3]),
                   "r"(b[0]), "r"(b[1]));
}
#define CP_ASYNC16(dst, src) \
    asm volatile("cp.async.cg.shared.global [%0], [%1], 16;" \
                 :: "r"(dst), "l"(src) : "memory")
#define CP_COMMIT() asm volatile("cp.async.commit_group;" ::: "memory")
#define CP_WAIT0()  asm volatile("cp.async.wait_group 0;" ::: "memory")
#define CP_WAIT1()  asm volatile("cp.async.wait_group 1;" ::: "memory")
#define CP_WAIT2()  asm volatile("cp.async.wait_group 2;" ::: "memory")

// ======================= pre-pass: round x, W to fp16 ========================
__global__ __launch_bounds__(256) void prepass_kernel(
    const float4* __restrict__ x,  const float4* __restrict__ wq,
    const float4* __restrict__ wk, const float4* __restrict__ wv,
    const float4* __restrict__ wo)
{
    int idx = blockIdx.x * 256 + threadIdx.x;   // 0 .. 2097151
    float4 v; uint2* dst;
    if (idx < 1048576) {
        v = x[idx]; dst = (uint2*)g_Xh + idx;
    } else {
        int r = idx - 1048576;
        int which = r >> 18, off = r & 262143;
        const float4* src = (which == 0) ? wq : (which == 1) ? wk
                          : (which == 2) ? wv : wo;
        v = src[off];
        dst = (uint2*)g_Wh + ((size_t)which << 18) + off;
    }
    uint2 o;
    o.x = pack2(v.x, v.y);
    o.y = pack2(v.z, v.w);
    *dst = o;
}

// ======================= fp16 GEMM (cp.async, 3-stage) =======================
// C[m,n] = sum_k A[m,k] * W[n,k]. Tile 128x128, BK=64 halfs, 8 warps (2m x 4n).
// m16n8k16 f16 mma, fp32 accumulate. 16 k-iterations, 3-stage cp.async ring.
#define PAH 72                            // pitch in halfs (144 B, ldsm-safe)
#define GTILEH (128 * PAH)                // halfs per tile
#define GSTAGEB (2 * GTILEH * 2)          // bytes per stage (A+B) = 36864
#define GSMEM (3 * GSTAGEB)               // 110592 B

__global__ void __launch_bounds__(256, 2) gemm_kernel(float* __restrict__ out,
                                                      int job)
{
    extern __shared__ __half smg[];
    const uint32_t sG = smem_u32(smg);

    const int tid = threadIdx.x;
    const int wid = tid >> 5, lane = tid & 31;
    const int wm = (wid >> 2) * 64;
    const int wn = (wid & 3) * 32;
    const int bm = blockIdx.y * 128;

    int bn, mode;
    const __half *Ap, *Wp;
    if (job == 0) {
        Ap = g_Oh; Wp = g_Wh + 3 * 1048576; mode = 0; bn = blockIdx.x * 128;
    } else {
        int which = blockIdx.x >> 3;
        bn = (blockIdx.x & 7) * 128;
        Ap = g_Xh; Wp = g_Wh + (size_t)which * 1048576;
        mode = (which == 2) ? 1 : which + 2;   // 0->Q(2), 1->K(3), 2->V(1)
    }

    const int q = lane >> 3, rq = lane & 7;
    const int qm = (q & 1) * 8;
    const uint32_t qk_b = (uint32_t)(q & 2) * 8;       // 0 or 16 bytes
    const int brow = (lane & 7) + ((lane >> 4) << 3);
    const uint32_t bcol_b = (uint32_t)((lane >> 3) & 1) * 16;

    // copy k-tile t (64 halfs wide) into stage s
    #define G_COPY(t, s) do {                                                  \
        uint32_t ab = sG + (uint32_t)((s) * GSTAGEB);                          \
        uint32_t bb = ab + (uint32_t)(GTILEH * 2);                             \
        int k0_ = (t) * 64;                                                    \
        _Pragma("unroll")                                                      \
        for (int i_ = 0; i_ < 4; i_++) {                                       \
            int f_ = tid + i_ * 256;                                           \
            int r_ = f_ >> 3, c_ = f_ & 7;                                     \
            uint32_t d_ = (uint32_t)(r_ * PAH + c_ * 8) * 2;                   \
            CP_ASYNC16(ab + d_, Ap + (size_t)(bm + r_) * DMODEL + k0_ + c_ * 8);\
            CP_ASYNC16(bb + d_, Wp + (size_t)(bn + r_) * DMODEL + k0_ + c_ * 8);\
        }                                                                      \
        CP_COMMIT();                                                           \
    } while (0)

    float acc[4][4][4];
    #pragma unroll
    for (int mt = 0; mt < 4; mt++)
        #pragma unroll
        for (int nt = 0; nt < 4; nt++)
            #pragma unroll
            for (int i = 0; i < 4; i++) acc[mt][nt][i] = 0.f;

    G_COPY(0, 0);
    G_COPY(1, 1);

    int stage = 0, nstage = 2;
    for (int t = 0; t < 16; t++) {
        if (t < 14) {
            G_COPY(t + 2, nstage);
            CP_WAIT2();
        } else if (t == 14) {
            CP_WAIT1();
        } else {
            CP_WAIT0();
        }
        __syncthreads();

        const uint32_t aB = sG + (uint32_t)(stage * GSTAGEB);
        const uint32_t bB = aB + (uint32_t)(GTILEH * 2);
        #pragma unroll
        for (int ks = 0; ks < 4; ks++) {
            uint32_t aR[4][4], b0[4], b1[4];
            #pragma unroll
            for (int mt = 0; mt < 4; mt++)
                ldsm4(aR[mt], aB + (uint32_t)((wm + mt * 16 + qm + rq) * PAH) * 2
                              + ks * 32 + qk_b);
            ldsm4(b0, bB + (uint32_t)((wn + brow) * PAH) * 2 + ks * 32 + bcol_b);
            ldsm4(b1, bB + (uint32_t)((wn + 16 + brow) * PAH) * 2 + ks * 32 + bcol_b);
            #pragma unroll
            for (int mt = 0; mt < 4; mt++) {
                mma_f16(acc[mt][0], aR[mt], &b0[0]);
                mma_f16(acc[mt][1], aR[mt], &b0[2]);
                mma_f16(acc[mt][2], aR[mt], &b1[0]);
                mma_f16(acc[mt][3], aR[mt], &b1[2]);
            }
        }
        __syncthreads();
        stage = (stage == 2) ? 0 : stage + 1;
        nstage = (nstage == 2) ? 0 : nstage + 1;
    }
    #undef G_COPY

    // ---------------- epilogue ------------------------------------------------
    const float kf = 0.28782313662425573f;   // ln(10000)/32
    #pragma unroll
    for (int mt = 0; mt < 4; mt++) {
        #pragma unroll
        for (int nt = 0; nt < 4; nt++) {
            float* a = acc[mt][nt];
            const int col = bn + wn + nt * 8 + 2 * (lane & 3);
            const int rbase = bm + wm + mt * 16 + (lane >> 2);
            if (mode == 0) {
                *(float2*)(out + (size_t)rbase * DMODEL + col) =
                    make_float2(a[0], a[1]);
                *(float2*)(out + (size_t)(rbase + 8) * DMODEL + col) =
                    make_float2(a[2], a[3]);
            } else if (mode == 1) {
                const int h = col >> 6, d = col & 63;
                #pragma unroll
                for (int rr = 0; rr < 2; rr++) {
                    int m = rbase + rr * 8;
                    int b = m >> 11, s = m & 2047;
                    __half* base = g_Vh + ((size_t)(b * NHEAD + h) * DK) * S_LEN;
                    base[(size_t)d * S_LEN + s]       = __float2half_rn(a[rr * 2]);
                    base[(size_t)(d + 1) * S_LEN + s] = __float2half_rn(a[rr * 2 + 1]);
                }
            } else {
                const int h = col >> 6, d = col & 63;
                const float qs = (mode == 2) ? 0.125f : 1.0f;
                __half* dst = (mode == 2) ? g_Qh : g_Kh;
                float fr = expf(-(float)(d >> 1) * kf);
                #pragma unroll
                for (int rr = 0; rr < 2; rr++) {
                    int m = rbase + rr * 8;
                    int b = m >> 11, s = m & 2047;
                    float e = a[rr * 2], o = a[rr * 2 + 1];
                    float sn, cs;
                    sincosf((float)s * fr, &sn, &cs);
                    __half2 v = __floats2half2_rn((e * cs - o * sn) * qs,
                                                  (e * sn + o * cs) * qs);
                    *(__half2*)(dst + ((size_t)(b * NHEAD + h) * S_LEN + s) * DK + d) = v;
                }
            }
        }
    }
}

// ================= causal flash attention, fp16 mma, kv-pipelined ============
// Iter j: softmax(S(j)) [tensor drains PV(j-1)] -> stage P -> S-mma(j+1) -> PV(j).
#define KPH 72
#define KV_TILE_B (64 * KPH * 2)          // 9216 B per K (or V^T) tile
#define BUF_B (2 * KV_TILE_B)             // 18432 B
#define PPH 72
#define FLASH_SMEM (2 * BUF_B + 128 * PPH * 2)   // 55296 B

__global__ void __launch_bounds__(256, 2) flash_kernel()
{
    extern __shared__ __half smf[];
    const uint32_t sK = smem_u32(smf);
    const uint32_t sP = sK + 2 * BUF_B;

    const int qt = 15 - blockIdx.y;     // big tiles first (bh fastest)
    const int bh = blockIdx.x;
    const __half* Qp  = g_Qh + (size_t)bh * S_LEN * DK;
    const __half* Kp  = g_Kh + (size_t)bh * S_LEN * DK;
    const __half* Vtp = g_Vh + (size_t)bh * S_LEN * DK;   // [d][s]

    const int tid = threadIdx.x;
    const int wid = tid >> 5, lane = tid & 31;
    const int q = lane >> 3, rq = lane & 7;
    const int qm = (q & 1) * 8;
    const uint32_t qk_b = (uint32_t)(q & 2) * 8;
    const int lq = lane >> 2, lc = lane & 3;
    const int brow = (lane & 7) + ((lane >> 4) << 3);
    const uint32_t bcol_b = (uint32_t)((lane >> 3) & 1) * 16;

    const int nkt = 2 * qt + 2;

    // K tile: 64 kv-rows x 64 halfs. V^T tile: 64 d-rows x 64 s-halfs.
    #define COPY_TILE(t, b) do {                                               \
        uint32_t kb = sK + (uint32_t)((b) * BUF_B);                            \
        uint32_t vb = kb + (uint32_t)KV_TILE_B;                                \
        _Pragma("unroll")                                                      \
        for (int i_ = 0; i_ < 2; i_++) {                                       \
            int f_ = tid + i_ * 256;                                           \
            int r_ = f_ >> 3, c_ = f_ & 7;                                     \
            uint32_t d_ = (uint32_t)(r_ * KPH + c_ * 8) * 2;                   \
            CP_ASYNC16(kb + d_, Kp + (size_t)((t) * 64 + r_) * DK + c_ * 8);   \
            CP_ASYNC16(vb + d_, Vtp + (size_t)r_ * S_LEN + (t) * 64 + c_ * 8); \
        }                                                                      \
        CP_COMMIT();                                                           \
    } while (0)

    #define S_MMA(b) do {                                                      \
        const uint32_t sKb_ = sK + (uint32_t)((b) * BUF_B);                    \
        _Pragma("unroll")                                                      \
        for (int nt_ = 0; nt_ < 8; nt_++)                                      \
            _Pragma("unroll")                                                  \
            for (int j_ = 0; j_ < 4; j_++) s[nt_][j_] = 0.f;                   \
        _Pragma("unroll")                                                      \
        for (int ks_ = 0; ks_ < 4; ks_++) {                                    \
            _Pragma("unroll")                                                  \
            for (int n2_ = 0; n2_ < 4; n2_++) {                                \
                uint32_t bb_[4];                                               \
                ldsm4(bb_, sKb_ + (uint32_t)((n2_ * 16 + brow) * KPH) * 2      \
                           + ks_ * 32 + bcol_b);                               \
                mma_f16(s[2 * n2_],     qf[ks_], &bb_[0]);                     \
                mma_f16(s[2 * n2_ + 1], qf[ks_], &bb_[2]);                     \
            }                                                                  \
        }                                                                      \
    } while (0)

    COPY_TILE(0, 0);
    COPY_TILE(1, 1);

    // stage Q tile (fp16) into P region and build fragments
    #pragma unroll
    for (int i = 0; i < 4; i++) {
        int f = tid + i * 256;
        int r = f >> 3, c = f & 7;
        uint4 v = *(const uint4*)(Qp + (size_t)(qt * 128 + r) * DK + c * 8);
        asm volatile("st.shared.v4.b32 [%0], {%1, %2, %3, %4};"
            :: "r"(sP + (uint32_t)(r * PPH + c * 8) * 2),
               "r"(v.x), "r"(v.y), "r"(v.z), "r"(v.w) : "memory");
    }
    __syncthreads();
    uint32_t qf[4][4];
    {
        uint32_t base = sP + (uint32_t)((wid * 16 + qm + rq) * PPH) * 2 + qk_b;
        #pragma unroll
        for (int ks = 0; ks < 4; ks++) ldsm4(qf[ks], base + ks * 32);
    }

    float m1 = -INFINITY, m2 = -INFINITY, l1 = 0.f, l2 = 0.f;
    float o[8][4];
    #pragma unroll
    for (int nt = 0; nt < 8; nt++)
        #pragma unroll
        for (int j = 0; j < 4; j++) o[nt][j] = 0.f;

    float s[8][4];
    CP_WAIT1();
    __syncthreads();
    S_MMA(0);

    for (int j = 0; j < nkt; j++) {
        if (j >= 2 * qt) {
            const int row1 = qt * 128 + wid * 16 + lq;
            #pragma unroll
            for (int nt = 0; nt < 8; nt++) {
                int colb = j * 64 + nt * 8 + 2 * lc;
                if (colb     > row1)     s[nt][0] = -INFINITY;
                if (colb + 1 > row1)     s[nt][1] = -INFINITY;
                if (colb     > row1 + 8) s[nt][2] = -INFINITY;
                if (colb + 1 > row1 + 8) s[nt][3] = -INFINITY;
            }
        }

        float mx1 = -INFINITY, mx2 = -INFINITY;
        #pragma unroll
        for (int nt = 0; nt < 8; nt++) {
            mx1 = fmaxf(mx1, fmaxf(s[nt][0], s[nt][1]));
            mx2 = fmaxf(mx2, fmaxf(s[nt][2], s[nt][3]));
        }
        mx1 = fmaxf(mx1, __shfl_xor_sync(0xffffffffu, mx1, 1));
        mx1 = fmaxf(mx1, __shfl_xor_sync(0xffffffffu, mx1, 2));
        mx2 = fmaxf(mx2, __shfl_xor_sync(0xffffffffu, mx2, 1));
        mx2 = fmaxf(mx2, __shfl_xor_sync(0xffffffffu, mx2, 2));
        const float nm1 = fmaxf(m1, mx1), nm2 = fmaxf(m2, mx2);
        const float sc1 = __expf(m1 - nm1), sc2 = __expf(m2 - nm2);
        float su1 = 0.f, su2 = 0.f;
        #pragma unroll
        for (int nt = 0; nt < 8; nt++) {
            s[nt][0] = __expf(s[nt][0] - nm1); su1 += s[nt][0];
            s[nt][1] = __expf(s[nt][1] - nm1); su1 += s[nt][1];
            s[nt][2] = __expf(s[nt][2] - nm2); su2 += s[nt][2];
            s[nt][3] = __expf(s[nt][3] - nm2); su2 += s[nt][3];
        }
        su1 += __shfl_xor_sync(0xffffffffu, su1, 1);
        su1 += __shfl_xor_sync(0xffffffffu, su1, 2);
        su2 += __shfl_xor_sync(0xffffffffu, su2, 1);
        su2 += __shfl_xor_sync(0xffffffffu, su2, 2);
        l1 = l1 * sc1 + su1;  m1 = nm1;
        l2 = l2 * sc2 + su2;  m2 = nm2;
        #pragma unroll
        for (int nt = 0; nt < 8; nt++) {
            o[nt][0] *= sc1; o[nt][1] *= sc1;
            o[nt][2] *= sc2; o[nt][3] *= sc2;
        }

        // ---- stage P(j) as fp16 (warp-private rows) ----
        {
            uint32_t p1 = sP + (uint32_t)((wid * 16 + lq) * PPH) * 2 + 4 * lc;
            uint32_t p2 = p1 + (uint32_t)(8 * PPH) * 2;
            #pragma unroll
            for (int nt = 0; nt < 8; nt++) {
                asm volatile("st.shared.b32 [%0], %1;"
                    :: "r"(p1 + nt * 16), "r"(pack2(s[nt][0], s[nt][1])) : "memory");
                asm volatile("st.shared.b32 [%0], %1;"
                    :: "r"(p2 + nt * 16), "r"(pack2(s[nt][2], s[nt][3])) : "memory");
            }
        }
        __syncwarp();

        if (j + 1 < nkt) {
            CP_WAIT0();
            __syncthreads();
            S_MMA((j + 1) & 1);
        }

        // ---- PV(j): O += P(j) * V(j) ----
        {
            const uint32_t sVb = sK + (uint32_t)((j & 1) * BUF_B + KV_TILE_B);
            uint32_t pbase = sP + (uint32_t)((wid * 16 + qm + rq) * PPH) * 2 + qk_b;
            #pragma unroll
            for (int ks = 0; ks < 4; ks++) {
                uint32_t pf[4];
                ldsm4(pf, pbase + ks * 32);
                #pragma unroll
                for (int n2 = 0; n2 < 4; n2++) {
                    uint32_t bb[4];
                    ldsm4(bb, sVb + (uint32_t)((n2 * 16 + brow) * KPH) * 2
                              + ks * 32 + bcol_b);
                    mma_f16(o[2 * n2],     pf, &bb[0]);
                    mma_f16(o[2 * n2 + 1], pf, &bb[2]);
                }
            }
        }

        __syncthreads();
        if (j + 2 < nkt) COPY_TILE(j + 2, j & 1);
    }

    // ---- normalize and write O as fp16 for the Wo GEMM ----
    const float i1 = 1.f / l1, i2 = 1.f / l2;
    const int b = bh >> 4, h = bh & 15;
    const int row1 = qt * 128 + wid * 16 + lq;
    const size_t base1 = ((size_t)(b * S_LEN + row1)) * DMODEL + h * 64 + 2 * lc;
    const size_t base2 = base1 + (size_t)8 * DMODEL;
    #pragma unroll
    for (int nt = 0; nt < 8; nt++) {
        *(__half2*)(g_Oh + base1 + nt * 8) =
            __floats2half2_rn(o[nt][0] * i1, o[nt][1] * i1);
        *(__half2*)(g_Oh + base2 + nt * 8) =
            __floats2half2_rn(o[nt][2] * i2, o[nt][3] * i2);
    }
    #undef COPY_TILE
    #undef S_MMA
}

// ------------------------- launch -------------------------------------------
extern "C" void kernel_launch(void* const* d_in, const int* in_sizes, int n_in,
                              void* d_out, int out_size)
{
    const float* x  = (const float*)d_in[0];
    const float* Wq = (const float*)d_in[1];
    const float* Wk = (const float*)d_in[2];
    const float* Wv = (const float*)d_in[3];
    const float* Wo = (const float*)d_in[4];
    float* out = (float*)d_out;

    cudaFuncSetAttribute(gemm_kernel,
                         cudaFuncAttributeMaxDynamicSharedMemorySize, GSMEM);
    cudaFuncSetAttribute(flash_kernel,
                         cudaFuncAttributeMaxDynamicSharedMemorySize, FLASH_SMEM);

    prepass_kernel<<<8192, 256>>>((const float4*)x, (const float4*)Wq,
                                  (const float4*)Wk, (const float4*)Wv,
                                  (const float4*)Wo);

    dim3 qkv_grid(24, 32);                   // 3 projections x 8 n-blocks
    gemm_kernel<<<qkv_grid, 256, GSMEM>>>(nullptr, 1);

    dim3 fgrid(32, 16);                      // bh fastest; qt = 15 - y
    flash_kernel<<<fgrid, 256, FLASH_SMEM>>>();

    dim3 ogrid(8, 32);
    gemm_kernel<<<ogrid, 256, GSMEM>>>(out, 0);
}